// round 14
// baseline (speedup 1.0000x reference)
#include <cuda_runtime.h>
#include <math.h>

constexpr int Nq   = 64;
constexpr int NXq  = 4096;
constexpr int NB   = 32;
constexpr int NT   = 1024;
constexpr int NIT  = 25;
constexpr int LDW  = 65;
constexpr float FEPS = 0.1f;
constexpr float FREG = 1e-9f;

struct SMem {
  float p[NXq], z[NXq], dv[NXq], rz[NXq], ds[NXq];
  float W[Nq * LDW];
  float cid[Nq];
  float fv[Nq], ev[Nq];
  float y[132], dyv[132];
  float u[Nq], iu[Nq], wd[Nq];
  float rde[Nq], rdee[Nq], rqe[Nq], rze[Nq], rr[Nq];
  float av[Nq], gvec[Nq], r1[Nq];
  float colp[6][16][Nq];
  float red[64];
};

__global__ void __launch_bounds__(NT, 1)
qp_ipm_kernel(const float* __restrict__ x, const float* __restrict__ gid,
              const float* __restrict__ expo, float* __restrict__ out) {
  extern __shared__ char smraw[];
  SMem* sm = reinterpret_cast<SMem*>(smraw);
  const int tid = threadIdx.x, lane = tid & 31, wid = tid >> 5;
  const int b = blockIdx.x;
  const unsigned FULL = 0xffffffffu;
  const int jc = tid & 63;
  const int ib = tid >> 6;          // 0..15 ; row for chunk j = ib + 16*j

  // ================= init =================
  #pragma unroll
  for (int j = 0; j < 4; ++j) {
    int k = tid + NT * j;
    sm->p[k] = x[b * NXq + k];
    sm->z[k] = 0.f;
  }
  if (tid < 132) sm->y[tid] = 0.f;
  if (tid < Nq) sm->ev[tid] = expo[tid];
  {
    float gv = (tid < Nq) ? gid[tid] : 0.f;
    #pragma unroll
    for (int o = 16; o; o >>= 1) gv += __shfl_down_sync(FULL, gv, o);
    if (lane == 0) sm->red[wid] = gv;
  }
  __syncthreads();
  {
    float gsum = sm->red[0] + sm->red[1];
    if (tid < Nq) {
      float g = gid[tid];
      sm->fv[tid] = g / gsum - (1.f - g) / (64.f - gsum);
    }
  }
  __syncthreads();

  float zr[4], s1[4], s2[4], l1[4], l2[4], fe[4], dzr[4];
  const float ej = sm->ev[jc];
  #pragma unroll
  for (int j = 0; j < 4; ++j) {
    zr[j] = 0.f; s1[j] = 1.f; s2[j] = 1.f; l1[j] = 1.f; l2[j] = 1.f;
    fe[j] = sm->fv[ib + 16 * j] * ej;
  }
  float musum = 8192.f;

  for (int it = 0; it < NIT; ++it) {
    const float smu = musum * (0.1f / 8192.f);

    // ---- P1: elementwise rhs_z, invD ----
    {
      const float yc = sm->y[64 + jc], yf = sm->y[128];
      #pragma unroll
      for (int j = 0; j < 4; ++j) {
        int i = ib + 16 * j, k = tid + NT * j;
        float aty = sm->y[i] + yc + yf * fe[j];
        float rdual = FEPS * zr[j] + sm->p[k] + aty - l1[j] + l2[j];
        float a1 = __fdividef(1.f, s1[j]);
        float a2 = __fdividef(1.f, s2[j]);
        float tmp1 = (smu - l1[j] * zr[j]) * a1;
        float tmp2 = (l2[j] * (zr[j] - 1.f) + smu) * a2;
        sm->rz[k] = tmp1 - tmp2 - rdual;
        sm->dv[k] = __fdividef(1.f, FEPS + l1[j] * a1 + l2[j] * a2);
      }
    }
    __syncthreads();  // B1

    // ---- P2: row reductions (warp w: rows 2w, 2w+1) ----
    {
      const float ejA = sm->ev[lane];
      const float ejB = sm->ev[lane + 32];
      #pragma unroll
      for (int rr2 = 0; rr2 < 2; ++rr2) {
        int i = wid * 2 + rr2;
        int k0 = i * 64 + lane, k1 = k0 + 32;
        float zA = sm->z[k0], zB = sm->z[k1];
        float dA = sm->dv[k0], dB = sm->dv[k1];
        float qA = dA * sm->rz[k0], qB = dB * sm->rz[k1];
        float zs = zA + zB;
        float ze = ejA * zA + ejB * zB;
        float dsum = dA + dB;
        float de = dA * ejA + dB * ejB;
        float dee = dA * ejA * ejA + dB * ejB * ejB;
        float qs = qA + qB;
        float qe = qA * ejA + qB * ejB;
        #pragma unroll
        for (int o = 16; o; o >>= 1) {
          zs   += __shfl_down_sync(FULL, zs, o);
          ze   += __shfl_down_sync(FULL, ze, o);
          dsum += __shfl_down_sync(FULL, dsum, o);
          de   += __shfl_down_sync(FULL, de, o);
          dee  += __shfl_down_sync(FULL, dee, o);
          qs   += __shfl_down_sync(FULL, qs, o);
          qe   += __shfl_down_sync(FULL, qe, o);
        }
        if (lane == 0) {
          float u = dsum + FREG;
          sm->u[i]    = u;
          sm->iu[i]   = 1.f / u;
          sm->rde[i]  = de;
          sm->av[i]   = sm->fv[i] * de;
          sm->rdee[i] = dee;
          sm->rze[i]  = ze;
          sm->rqe[i]  = qe;
          sm->rr[i]   = qs + (zs - 1.f);
        }
      }
    }
    __syncthreads();  // B2

    // ---- P3: fair partials (warps 0-1) + column reductions ----
    if (wid < 2) {
      float f = sm->fv[tid], a = sm->av[tid], iuv = sm->iu[tid];
      float p0 = f * f * sm->rdee[tid];
      float p1 = f * (sm->rqe[tid] + sm->rze[tid]);
      float p2 = a * a * iuv;
      float p3 = a * iuv * sm->rr[tid];
      float p4 = sm->u[tid];
      #pragma unroll
      for (int o = 16; o; o >>= 1) {
        p0 += __shfl_down_sync(FULL, p0, o);
        p1 += __shfl_down_sync(FULL, p1, o);
        p2 += __shfl_down_sync(FULL, p2, o);
        p3 += __shfl_down_sync(FULL, p3, o);
        p4 += __shfl_down_sync(FULL, p4, o);
      }
      if (lane == 0) {
        sm->red[wid * 8 + 0] = p0; sm->red[wid * 8 + 1] = p1;
        sm->red[wid * 8 + 2] = p2; sm->red[wid * 8 + 3] = p3;
        sm->red[wid * 8 + 4] = p4;
      }
    }
    {
      int c = tid & 63, ip = tid >> 6;     // ip 0..15, 4 rows each
      float cz = 0, cd = 0, cdf = 0, cq = 0, cdia = 0, cdir = 0;
      #pragma unroll
      for (int m = 0; m < 4; ++m) {
        int i = ip * 4 + m, k = i * 64 + c;
        float dk = sm->dv[k];
        float qk = dk * sm->rz[k];
        float wi = sm->iu[i];
        float dw = dk * wi;
        sm->ds[k] = dw;
        cz += sm->z[k]; cd += dk; cdf += dk * sm->fv[i]; cq += qk;
        cdia += dw * sm->av[i];
        cdir += dw * sm->rr[i];
      }
      sm->colp[0][ip][c] = cz;  sm->colp[1][ip][c] = cd;   sm->colp[2][ip][c] = cdf;
      sm->colp[3][ip][c] = cq;  sm->colp[4][ip][c] = cdia; sm->colp[5][ip][c] = cdir;
    }
    __syncthreads();  // B3

    const float sff   = sm->red[0] + sm->red[8] + FREG;
    const float rfair = sm->red[1] + sm->red[9];
    const float gam   = sff - (sm->red[2] + sm->red[10]);
    const float r2v   = rfair - (sm->red[3] + sm->red[11]);
    const float rho   = (sm->red[4] + sm->red[12]) * (1e-3f / 64.f);

    // ---- P4: finals + W lower-triangle formation ----
    if (tid < Nq) {
      int c = tid;
      float colz = 0, cold = 0, coldf = 0, colq = 0, cdia = 0, cdir = 0;
      #pragma unroll
      for (int m = 0; m < 16; ++m) {
        colz += sm->colp[0][m][c]; cold += sm->colp[1][m][c];
        coldf += sm->colp[2][m][c]; colq += sm->colp[3][m][c];
        cdia += sm->colp[4][m][c]; cdir += sm->colp[5][m][c];
      }
      sm->wd[c]   = cold + FREG;
      sm->gvec[c] = sm->ev[c] * coldf - cdia;
      sm->r1[c]   = colq + (colz - 1.f) - cdir;
    }
    if (tid < 272) {
      float ft = (float)(4 * tid + 1);
      int R = (int)((sqrtf(ft) - 1.f) * 0.5f);
      int C = tid - R * (R + 1);
      int c1 = R * 4;
      int c2 = C * 2;
      float a00 = 0, a01 = 0, a10 = 0, a11 = 0, a20 = 0, a21 = 0, a30 = 0, a31 = 0;
      for (int i = 0; i < Nq; ++i) {
        float4 av4 = *reinterpret_cast<const float4*>(&sm->ds[i * 64 + c1]);
        float2 bb  = *reinterpret_cast<const float2*>(&sm->dv[i * 64 + c2]);
        a00 += av4.x * bb.x; a01 += av4.x * bb.y;
        a10 += av4.y * bb.x; a11 += av4.y * bb.y;
        a20 += av4.z * bb.x; a21 += av4.z * bb.y;
        a30 += av4.w * bb.x; a31 += av4.w * bb.y;
      }
      sm->W[(c1 + 0) * LDW + c2]     = rho - a00;
      sm->W[(c1 + 0) * LDW + c2 + 1] = rho - a01;
      sm->W[(c1 + 1) * LDW + c2]     = rho - a10;
      sm->W[(c1 + 1) * LDW + c2 + 1] = rho - a11;
      sm->W[(c1 + 2) * LDW + c2]     = rho - a20;
      sm->W[(c1 + 2) * LDW + c2 + 1] = rho - a21;
      sm->W[(c1 + 3) * LDW + c2]     = rho - a30;
      sm->W[(c1 + 3) * LDW + c2 + 1] = rho - a31;
    }
    __syncthreads();  // B4

    // ---- P5a: blocked Cholesky — lookahead, rank-2 diag factor ----
    #pragma unroll 1
    for (int p = 0; p < 8; ++p) {
      const int k0 = p * 8, ts = k0 + 8, kp = k0 - 8;
      if (p > 0) {
        int npair = (Nq - k0) << 3;
        if (tid < npair) {
          int r = k0 + (tid >> 3);
          int c = k0 + (tid & 7);
          if (c <= r) {
            float acc = 0.f;
            #pragma unroll
            for (int t = 0; t < 8; ++t)
              acc += sm->W[r * LDW + kp + t] * sm->W[c * LDW + kp + t];
            sm->W[r * LDW + c] -= acc;
          }
        }
        __syncthreads();  // SA
      }

      // T2 || T4
      if (wid == 0) {
        float a[8], dreg[8];
        #pragma unroll
        for (int c = 0; c < 8; ++c) a[c] = 0.f;
        if (lane < 8) {
          #pragma unroll
          for (int c = 0; c < 8; ++c) {
            if (c < lane)  a[c] = sm->W[(k0 + lane) * LDW + k0 + c];
            if (c == lane) a[c] = sm->W[(k0 + lane) * LDW + k0 + c] + sm->wd[k0 + lane];
          }
        }
        #pragma unroll
        for (int j = 0; j < 8; j += 2) {
          const int j1 = j + 1;
          float aj  = a[j];
          float aj1 = a[j1];
          float dj  = fmaxf(__shfl_sync(FULL, aj, j), 1e-12f);
          float lj1 = __shfl_sync(FULL, aj, j1);
          float tj1 = __shfl_sync(FULL, aj1, j1);
          float invdj = __fdividef(1.f, dj);
          float f1 = lj1 * invdj;
          float dj1 = fmaxf(tj1 - lj1 * f1, 1e-12f);
          float invdj1 = __fdividef(1.f, dj1);
          float aj1n = aj1 - aj * f1;
          a[j1] = aj1n;
          dreg[j] = dj; dreg[j1] = dj1;
          #pragma unroll
          for (int c2 = j + 2; c2 < 8; ++c2) {
            float lcj  = __shfl_sync(FULL, aj, c2);
            float tcj1 = __shfl_sync(FULL, aj1, c2);
            float lcj1 = tcj1 - lcj * f1;
            a[c2] -= aj * (lcj * invdj) + aj1n * (lcj1 * invdj1);
          }
        }
        #pragma unroll
        for (int j = 0; j < 8; ++j) dreg[j] = rsqrtf(dreg[j]);
        if (lane == 0) {
          #pragma unroll
          for (int j = 0; j < 8; ++j) sm->cid[k0 + j] = dreg[j];
        }
        if (lane < 8) {
          #pragma unroll
          for (int c = 0; c < 8; ++c)
            if (c <= lane) sm->W[(k0 + lane) * LDW + k0 + c] = a[c] * dreg[c];
        }
      } else if (wid >= 2 && p > 0 && ts < Nq) {
        int w2 = wid - 2;               // 0..29
        int cs = w2 & 1, rg = w2 >> 1;  // rg 0..14, stride 15
        int c = ts + cs * 32 + lane;
        bool cok = (c < Nq);
        float cv[8];
        if (cok) {
          #pragma unroll
          for (int t = 0; t < 8; ++t) cv[t] = sm->W[c * LDW + kp + t];
        }
        for (int r = ts + rg; r < Nq; r += 15) {
          if (cok && c <= r) {
            float acc = 0.f;
            #pragma unroll
            for (int t = 0; t < 8; ++t)
              acc += sm->W[r * LDW + kp + t] * cv[t];
            sm->W[r * LDW + c] -= acc;
          }
        }
      }
      __syncthreads();  // SB

      if (p < 7) {
        const int m = Nq - ts;
        if (tid < m) {
          int r = ts + tid;
          float v[8];
          #pragma unroll
          for (int c = 0; c < 8; ++c) v[c] = sm->W[r * LDW + k0 + c];
          #pragma unroll
          for (int j = 0; j < 8; ++j) {
            float acc = v[j];
            #pragma unroll
            for (int q = 0; q < j; ++q)
              acc -= v[q] * sm->W[(k0 + j) * LDW + k0 + q];
            v[j] = acc * sm->cid[k0 + j];
          }
          #pragma unroll
          for (int c = 0; c < 8; ++c) sm->W[r * LDW + k0 + c] = v[c];
        }
        __syncthreads();  // SC
      }
    }

    // ---- P5b: warp0 — rank-2 triangular solves + fair Schur ----
    if (wid == 0) {
      float x1a = sm->r1[lane],   x1b = sm->r1[lane + 32];
      float x2a = sm->gvec[lane], x2b = sm->gvec[lane + 32];
      for (int k = 0; k < 32; k += 2) {
        float ck0 = sm->cid[k], ck1 = sm->cid[k + 1];
        float L10 = sm->W[(k + 1) * LDW + k];
        float y10 = __shfl_sync(FULL, x1a, k) * ck0;
        float y20 = __shfl_sync(FULL, x2a, k) * ck0;
        float t11 = __shfl_sync(FULL, x1a, k + 1);
        float t21 = __shfl_sync(FULL, x2a, k + 1);
        float y11 = (t11 - L10 * y10) * ck1;
        float y21 = (t21 - L10 * y20) * ck1;
        if (lane == k)     { x1a = y10; x2a = y20; }
        if (lane == k + 1) { x1a = y11; x2a = y21; }
        float wa0 = (lane > k + 1) ? sm->W[lane * LDW + k]     : 0.f;
        float wa1 = (lane > k + 1) ? sm->W[lane * LDW + k + 1] : 0.f;
        float wb0 = sm->W[(lane + 32) * LDW + k];
        float wb1 = sm->W[(lane + 32) * LDW + k + 1];
        x1a -= wa0 * y10 + wa1 * y11;
        x2a -= wa0 * y20 + wa1 * y21;
        x1b -= wb0 * y10 + wb1 * y11;
        x2b -= wb0 * y20 + wb1 * y21;
      }
      for (int k = 32; k < 64; k += 2) {
        float ck0 = sm->cid[k], ck1 = sm->cid[k + 1];
        float L10 = sm->W[(k + 1) * LDW + k];
        float y10 = __shfl_sync(FULL, x1b, k - 32) * ck0;
        float y20 = __shfl_sync(FULL, x2b, k - 32) * ck0;
        float t11 = __shfl_sync(FULL, x1b, k - 31);
        float t21 = __shfl_sync(FULL, x2b, k - 31);
        float y11 = (t11 - L10 * y10) * ck1;
        float y21 = (t21 - L10 * y20) * ck1;
        if (lane == k - 32) { x1b = y10; x2b = y20; }
        if (lane == k - 31) { x1b = y11; x2b = y21; }
        float wb0 = (lane + 32 > k + 1) ? sm->W[(lane + 32) * LDW + k]     : 0.f;
        float wb1 = (lane + 32 > k + 1) ? sm->W[(lane + 32) * LDW + k + 1] : 0.f;
        x1b -= wb0 * y10 + wb1 * y11;
        x2b -= wb0 * y20 + wb1 * y21;
      }
      for (int k = 63; k >= 33; k -= 2) {
        float ck0 = sm->cid[k], ck1 = sm->cid[k - 1];
        float Lk = sm->W[k * LDW + k - 1];
        float y10 = __shfl_sync(FULL, x1b, k - 32) * ck0;
        float y20 = __shfl_sync(FULL, x2b, k - 32) * ck0;
        float t11 = __shfl_sync(FULL, x1b, k - 33);
        float t21 = __shfl_sync(FULL, x2b, k - 33);
        float y11 = (t11 - Lk * y10) * ck1;
        float y21 = (t21 - Lk * y20) * ck1;
        if (lane == k - 32) { x1b = y10; x2b = y20; }
        if (lane == k - 33) { x1b = y11; x2b = y21; }
        float wa0 = sm->W[k * LDW + lane];
        float wa1 = sm->W[(k - 1) * LDW + lane];
        float wb0 = (lane + 32 < k - 1) ? sm->W[k * LDW + lane + 32]       : 0.f;
        float wb1 = (lane + 32 < k - 1) ? sm->W[(k - 1) * LDW + lane + 32] : 0.f;
        x1a -= wa0 * y10 + wa1 * y11;
        x2a -= wa0 * y20 + wa1 * y21;
        x1b -= wb0 * y10 + wb1 * y11;
        x2b -= wb0 * y20 + wb1 * y21;
      }
      for (int k = 31; k >= 1; k -= 2) {
        float ck0 = sm->cid[k], ck1 = sm->cid[k - 1];
        float Lk = sm->W[k * LDW + k - 1];
        float y10 = __shfl_sync(FULL, x1a, k) * ck0;
        float y20 = __shfl_sync(FULL, x2a, k) * ck0;
        float t11 = __shfl_sync(FULL, x1a, k - 1);
        float t21 = __shfl_sync(FULL, x2a, k - 1);
        float y11 = (t11 - Lk * y10) * ck1;
        float y21 = (t21 - Lk * y20) * ck1;
        if (lane == k)     { x1a = y10; x2a = y20; }
        if (lane == k - 1) { x1a = y11; x2a = y21; }
        float wa0 = (lane < k - 1) ? sm->W[k * LDW + lane]       : 0.f;
        float wa1 = (lane < k - 1) ? sm->W[(k - 1) * LDW + lane] : 0.f;
        x1a -= wa0 * y10 + wa1 * y11;
        x2a -= wa0 * y20 + wa1 * y21;
      }
      float g1 = sm->gvec[lane] * x1a + sm->gvec[lane + 32] * x1b;
      float g2 = sm->gvec[lane] * x2a + sm->gvec[lane + 32] * x2b;
      #pragma unroll
      for (int o = 16; o; o >>= 1) {
        g1 += __shfl_down_sync(FULL, g1, o);
        g2 += __shfl_down_sync(FULL, g2, o);
      }
      g1 = __shfl_sync(FULL, g1, 0);
      g2 = __shfl_sync(FULL, g2, 0);
      float dyf = (r2v - g1) / (gam - g2);
      sm->dyv[64 + lane] = x1a - dyf * x2a;
      sm->dyv[96 + lane] = x1b - dyf * x2b;
      if (lane == 0) sm->dyv[128] = dyf;
    }
    __syncthreads();  // B5

    // ---- P6: row duals (warp w: rows 2w, 2w+1) ----
    {
      float dyf = sm->dyv[128];
      float dca = sm->dyv[64 + lane], dcb = sm->dyv[96 + lane];
      #pragma unroll
      for (int rr2 = 0; rr2 < 2; ++rr2) {
        int i = wid * 2 + rr2;
        float dot = sm->dv[i * 64 + lane] * dca + sm->dv[i * 64 + lane + 32] * dcb;
        #pragma unroll
        for (int o = 16; o; o >>= 1) dot += __shfl_down_sync(FULL, dot, o);
        if (lane == 0)
          sm->dyv[i] = (sm->rr[i] - dot - sm->av[i] * dyf) * sm->iu[i];
      }
    }
    __syncthreads();  // B6

    // ---- P7: dz + step length ----
    float amin = 1e30f;
    {
      float maxs = 1e-30f;
      float dyf = sm->dyv[128];
      float dyc = sm->dyv[64 + jc];
      #pragma unroll
      for (int j = 0; j < 4; ++j) {
        int i = ib + 16 * j, k = tid + NT * j;
        float atd = sm->dyv[i] + dyc + dyf * fe[j];
        float dzk = (sm->rz[k] - atd) * sm->dv[k];
        dzr[j] = dzk;
        float a1 = __fdividef(1.f, s1[j]);
        float a2 = __fdividef(1.f, s2[j]);
        float ds1 = zr[j] - s1[j] + dzk;
        float ds2 = 1.f - zr[j] - s2[j] - dzk;
        float dl1 = smu * a1 - l1[j] - l1[j] * ds1 * a1;
        float dl2 = smu * a2 - l2[j] - l2[j] * ds2 * a2;
        maxs = fmaxf(maxs, fmaxf(-ds1 * a1, -ds2 * a2));
        if (dl1 < 0.f) amin = fminf(amin, __fdividef(l1[j], -dl1));
        if (dl2 < 0.f) amin = fminf(amin, __fdividef(l2[j], -dl2));
      }
      amin = fminf(amin, __fdividef(1.f, maxs));
    }
    #pragma unroll
    for (int o = 16; o; o >>= 1) amin = fminf(amin, __shfl_down_sync(FULL, amin, o));
    if (lane == 0) sm->red[32 + wid] = amin;
    __syncthreads();  // B7
    float am = 1e30f;
    #pragma unroll
    for (int w = 0; w < 32; ++w) am = fminf(am, sm->red[32 + w]);
    const float alpha = fminf(1.f, 0.99f * am);

    // ---- P8: update + mu accumulation ----
    float sl = 0.f;
    #pragma unroll
    for (int j = 0; j < 4; ++j) {
      int k = tid + NT * j;
      float dzk = dzr[j];
      float a1 = __fdividef(1.f, s1[j]);
      float a2 = __fdividef(1.f, s2[j]);
      float ds1 = zr[j] - s1[j] + dzk;
      float ds2 = 1.f - zr[j] - s2[j] - dzk;
      float dl1 = smu * a1 - l1[j] - l1[j] * ds1 * a1;
      float dl2 = smu * a2 - l2[j] - l2[j] * ds2 * a2;
      zr[j] += alpha * dzk;
      s1[j] += alpha * ds1;  s2[j] += alpha * ds2;
      l1[j] += alpha * dl1;  l2[j] += alpha * dl2;
      sm->z[k] = zr[j];
      sl += s1[j] * l1[j] + s2[j] * l2[j];
    }
    if (tid < 129) sm->y[tid] += alpha * sm->dyv[tid];
    #pragma unroll
    for (int o = 16; o; o >>= 1) sl += __shfl_down_sync(FULL, sl, o);
    if (lane == 0) sm->red[wid] = sl;
    __syncthreads();  // B8
    musum = 0.f;
    #pragma unroll
    for (int w = 0; w < 32; ++w) musum += sm->red[w];
  }

  #pragma unroll
  for (int j = 0; j < 4; ++j)
    out[b * NXq + tid + NT * j] = zr[j];
}

extern "C" void kernel_launch(void* const* d_in, const int* in_sizes, int n_in,
                              void* d_out, int out_size) {
  const float* x    = (const float*)d_in[0];
  const float* gid  = (const float*)d_in[1];
  const float* expo = (const float*)d_in[2];
  float* out = (float*)d_out;
  size_t smem = sizeof(SMem);
  cudaFuncSetAttribute(qp_ipm_kernel,
                       cudaFuncAttributeMaxDynamicSharedMemorySize, (int)smem);
  qp_ipm_kernel<<<NB, NT, smem>>>(x, gid, expo, out);
}

// round 15
// speedup vs baseline: 1.2349x; 1.2349x over previous
#include <cuda_runtime.h>
#include <math.h>

constexpr int Nq   = 64;
constexpr int NXq  = 4096;
constexpr int NB   = 32;
constexpr int NT   = 512;
constexpr int NIT  = 25;
constexpr int LDW  = 65;
constexpr float FEPS = 0.1f;
constexpr float FREG = 1e-9f;

struct SMem {
  float p[NXq], z[NXq], dv[NXq], rz[NXq], ds[NXq];
  float W[66 * LDW];            // rows 64,65 = augmented RHS (r1, gvec)
  float cid[Nq];
  float fv[Nq], ev[Nq];
  float y[132], dyv[132];
  float u[Nq], iu[Nq], wd[Nq];
  float rde[Nq], rdee[Nq], rqe[Nq], rze[Nq], rr[Nq];
  float av[Nq], gvec[Nq], r1[Nq];
  float colp[6][8][Nq];
  float red[64];
};

__global__ void __launch_bounds__(NT, 1)
qp_ipm_kernel(const float* __restrict__ x, const float* __restrict__ gid,
              const float* __restrict__ expo, float* __restrict__ out) {
  extern __shared__ char smraw[];
  SMem* sm = reinterpret_cast<SMem*>(smraw);
  const int tid = threadIdx.x, lane = tid & 31, wid = tid >> 5;
  const int b = blockIdx.x;
  const unsigned FULL = 0xffffffffu;
  const int jc = tid & 63;
  const int ib = tid >> 6;

  // ================= init =================
  #pragma unroll
  for (int j = 0; j < 8; ++j) {
    int k = tid + NT * j;
    sm->p[k] = x[b * NXq + k];
    sm->z[k] = 0.f;
  }
  if (tid < 132) sm->y[tid] = 0.f;
  if (tid < Nq) sm->ev[tid] = expo[tid];
  {
    float gv = (tid < Nq) ? gid[tid] : 0.f;
    #pragma unroll
    for (int o = 16; o; o >>= 1) gv += __shfl_down_sync(FULL, gv, o);
    if (lane == 0) sm->red[wid] = gv;
  }
  __syncthreads();
  {
    float gsum = sm->red[0] + sm->red[1];
    if (tid < Nq) {
      float g = gid[tid];
      sm->fv[tid] = g / gsum - (1.f - g) / (64.f - gsum);
    }
  }
  __syncthreads();

  float zr[8], s1[8], s2[8], l1[8], l2[8], fe[8], is1[8], is2[8], dzr[8];
  const float ej  = sm->ev[jc];
  const float ejA = sm->ev[lane];
  const float ejB = sm->ev[lane + 32];
  #pragma unroll
  for (int j = 0; j < 8; ++j) {
    zr[j] = 0.f; s1[j] = 1.f; s2[j] = 1.f; l1[j] = 1.f; l2[j] = 1.f;
    fe[j] = sm->fv[ib + 8 * j] * ej;
  }
  float musum = 8192.f;

  for (int it = 0; it < NIT; ++it) {
    const float smu = musum * (0.1f / 8192.f);

    // ---- P1: elementwise rhs_z, invD ----
    {
      const float yc = sm->y[64 + jc], yf = sm->y[128];
      #pragma unroll
      for (int j = 0; j < 8; ++j) {
        int i = ib + 8 * j, k = tid + NT * j;
        float aty = sm->y[i] + yc + yf * fe[j];
        float rdual = FEPS * zr[j] + sm->p[k] + aty - l1[j] + l2[j];
        float a1 = __fdividef(1.f, s1[j]);
        float a2 = __fdividef(1.f, s2[j]);
        is1[j] = a1; is2[j] = a2;
        float tmp1 = (smu - l1[j] * zr[j]) * a1;
        float tmp2 = (l2[j] * (zr[j] - 1.f) + smu) * a2;
        sm->rz[k] = tmp1 - tmp2 - rdual;
        sm->dv[k] = __fdividef(1.f, FEPS + l1[j] * a1 + l2[j] * a2);
      }
    }
    __syncthreads();  // B1

    // ---- P2: row reductions ----
    #pragma unroll
    for (int rr4 = 0; rr4 < 4; ++rr4) {
      int i = wid * 4 + rr4;
      int k0 = i * 64 + lane, k1 = k0 + 32;
      float zA = sm->z[k0], zB = sm->z[k1];
      float dA = sm->dv[k0], dB = sm->dv[k1];
      float qA = dA * sm->rz[k0], qB = dB * sm->rz[k1];
      float zs = zA + zB;
      float ze = ejA * zA + ejB * zB;
      float dsum = dA + dB;
      float de = dA * ejA + dB * ejB;
      float dee = dA * ejA * ejA + dB * ejB * ejB;
      float qs = qA + qB;
      float qe = qA * ejA + qB * ejB;
      #pragma unroll
      for (int o = 16; o; o >>= 1) {
        zs   += __shfl_down_sync(FULL, zs, o);
        ze   += __shfl_down_sync(FULL, ze, o);
        dsum += __shfl_down_sync(FULL, dsum, o);
        de   += __shfl_down_sync(FULL, de, o);
        dee  += __shfl_down_sync(FULL, dee, o);
        qs   += __shfl_down_sync(FULL, qs, o);
        qe   += __shfl_down_sync(FULL, qe, o);
      }
      if (lane == 0) {
        float u = dsum + FREG;
        sm->u[i]    = u;
        sm->iu[i]   = 1.f / u;
        sm->rde[i]  = de;
        sm->av[i]   = sm->fv[i] * de;
        sm->rdee[i] = dee;
        sm->rze[i]  = ze;
        sm->rqe[i]  = qe;
        sm->rr[i]   = qs + (zs - 1.f);
      }
    }
    __syncthreads();  // B2

    // ---- P3: fair partials + column reductions (+ ds precompute) ----
    if (wid < 2) {
      float f = sm->fv[tid], a = sm->av[tid], iuv = sm->iu[tid];
      float p0 = f * f * sm->rdee[tid];
      float p1 = f * (sm->rqe[tid] + sm->rze[tid]);
      float p2 = a * a * iuv;
      float p3 = a * iuv * sm->rr[tid];
      float p4 = sm->u[tid];
      #pragma unroll
      for (int o = 16; o; o >>= 1) {
        p0 += __shfl_down_sync(FULL, p0, o);
        p1 += __shfl_down_sync(FULL, p1, o);
        p2 += __shfl_down_sync(FULL, p2, o);
        p3 += __shfl_down_sync(FULL, p3, o);
        p4 += __shfl_down_sync(FULL, p4, o);
      }
      if (lane == 0) {
        sm->red[wid * 8 + 0] = p0; sm->red[wid * 8 + 1] = p1;
        sm->red[wid * 8 + 2] = p2; sm->red[wid * 8 + 3] = p3;
        sm->red[wid * 8 + 4] = p4;
      }
    }
    {
      int c = tid & 63, ip = tid >> 6;
      float cz = 0, cd = 0, cdf = 0, cq = 0, cdia = 0, cdir = 0;
      #pragma unroll
      for (int m = 0; m < 8; ++m) {
        int i = ip * 8 + m, k = i * 64 + c;
        float dk = sm->dv[k];
        float qk = dk * sm->rz[k];
        float wi = sm->iu[i];
        float dw = dk * wi;
        sm->ds[k] = dw;
        cz += sm->z[k]; cd += dk; cdf += dk * sm->fv[i]; cq += qk;
        cdia += dw * sm->av[i];
        cdir += dw * sm->rr[i];
      }
      sm->colp[0][ip][c] = cz;  sm->colp[1][ip][c] = cd;   sm->colp[2][ip][c] = cdf;
      sm->colp[3][ip][c] = cq;  sm->colp[4][ip][c] = cdia; sm->colp[5][ip][c] = cdir;
    }
    __syncthreads();  // B3

    const float sff   = sm->red[0] + sm->red[8] + FREG;
    const float rfair = sm->red[1] + sm->red[9];
    const float gam   = sff - (sm->red[2] + sm->red[10]);
    const float r2v   = rfair - (sm->red[3] + sm->red[11]);
    const float rho   = (sm->red[4] + sm->red[12]) * (1e-3f / 64.f);

    // ---- P4: finals + W lower-triangle + augmented RHS rows ----
    if (tid < Nq) {
      int c = tid;
      float colz = 0, cold = 0, coldf = 0, colq = 0, cdia = 0, cdir = 0;
      #pragma unroll
      for (int m = 0; m < 8; ++m) {
        colz += sm->colp[0][m][c]; cold += sm->colp[1][m][c];
        coldf += sm->colp[2][m][c]; colq += sm->colp[3][m][c];
        cdia += sm->colp[4][m][c]; cdir += sm->colp[5][m][c];
      }
      float gv = sm->ev[c] * coldf - cdia;
      float rv = colq + (colz - 1.f) - cdir;
      sm->wd[c]   = cold + FREG;
      sm->gvec[c] = gv;
      sm->W[64 * LDW + c] = rv;   // augmented row: r1
      sm->W[65 * LDW + c] = gv;   // augmented row: gvec
    }
    if (tid < 272) {
      float ft = (float)(4 * tid + 1);
      int R = (int)((sqrtf(ft) - 1.f) * 0.5f);
      int C = tid - R * (R + 1);
      int c1 = R * 4;
      int c2 = C * 2;
      float a00 = 0, a01 = 0, a10 = 0, a11 = 0, a20 = 0, a21 = 0, a30 = 0, a31 = 0;
      for (int i = 0; i < Nq; ++i) {
        float4 av4 = *reinterpret_cast<const float4*>(&sm->ds[i * 64 + c1]);
        float2 bb  = *reinterpret_cast<const float2*>(&sm->dv[i * 64 + c2]);
        a00 += av4.x * bb.x; a01 += av4.x * bb.y;
        a10 += av4.y * bb.x; a11 += av4.y * bb.y;
        a20 += av4.z * bb.x; a21 += av4.z * bb.y;
        a30 += av4.w * bb.x; a31 += av4.w * bb.y;
      }
      sm->W[(c1 + 0) * LDW + c2]     = rho - a00;
      sm->W[(c1 + 0) * LDW + c2 + 1] = rho - a01;
      sm->W[(c1 + 1) * LDW + c2]     = rho - a10;
      sm->W[(c1 + 1) * LDW + c2 + 1] = rho - a11;
      sm->W[(c1 + 2) * LDW + c2]     = rho - a20;
      sm->W[(c1 + 2) * LDW + c2 + 1] = rho - a21;
      sm->W[(c1 + 3) * LDW + c2]     = rho - a30;
      sm->W[(c1 + 3) * LDW + c2 + 1] = rho - a31;
    }
    __syncthreads();  // B4

    // ---- P5a: blocked Cholesky + fused forward solve (augmented rows) ----
    #pragma unroll 1
    for (int p = 0; p < 8; ++p) {
      const int k0 = p * 8, ts = k0 + 8, kp = k0 - 8;
      // T1: correct column block p (rows >= k0 and augmented) with panel p-1
      if (p > 0) {
        int npair = (Nq - k0 + 2) << 3;
        if (tid < npair) {
          int rr = k0 + (tid >> 3);
          int c = k0 + (tid & 7);
          bool app = (rr >= Nq);
          int r = app ? (64 + rr - Nq) : rr;
          if (app || c <= r) {
            float acc = 0.f;
            #pragma unroll
            for (int t = 0; t < 8; ++t)
              acc += sm->W[r * LDW + kp + t] * sm->W[c * LDW + kp + t];
            sm->W[r * LDW + c] -= acc;
          }
        }
        __syncthreads();  // SA
      }

      // T2 || T4
      if (wid == 0) {
        float a[8], dreg[8];
        #pragma unroll
        for (int c = 0; c < 8; ++c) a[c] = 0.f;
        if (lane < 8) {
          #pragma unroll
          for (int c = 0; c < 8; ++c) {
            if (c < lane)  a[c] = sm->W[(k0 + lane) * LDW + k0 + c];
            if (c == lane) a[c] = sm->W[(k0 + lane) * LDW + k0 + c] + sm->wd[k0 + lane];
          }
        }
        #pragma unroll
        for (int j = 0; j < 8; j += 2) {
          const int j1 = j + 1;
          float aj  = a[j];
          float aj1 = a[j1];
          float dj  = fmaxf(__shfl_sync(FULL, aj, j), 1e-12f);
          float lj1 = __shfl_sync(FULL, aj, j1);
          float tj1 = __shfl_sync(FULL, aj1, j1);
          float invdj = __fdividef(1.f, dj);
          float f1 = lj1 * invdj;
          float dj1 = fmaxf(tj1 - lj1 * f1, 1e-12f);
          float invdj1 = __fdividef(1.f, dj1);
          float aj1n = aj1 - aj * f1;
          a[j1] = aj1n;
          dreg[j] = dj; dreg[j1] = dj1;
          #pragma unroll
          for (int c2 = j + 2; c2 < 8; ++c2) {
            float lcj  = __shfl_sync(FULL, aj, c2);
            float tcj1 = __shfl_sync(FULL, aj1, c2);
            float lcj1 = tcj1 - lcj * f1;
            a[c2] -= aj * (lcj * invdj) + aj1n * (lcj1 * invdj1);
          }
        }
        #pragma unroll
        for (int j = 0; j < 8; ++j) dreg[j] = rsqrtf(dreg[j]);
        if (lane == 0) {
          #pragma unroll
          for (int j = 0; j < 8; ++j) sm->cid[k0 + j] = dreg[j];
        }
        if (lane < 8) {
          #pragma unroll
          for (int c = 0; c < 8; ++c)
            if (c <= lane) sm->W[(k0 + lane) * LDW + k0 + c] = a[c] * dreg[c];
        }
      } else if (wid >= 2 && p > 0 && ts < Nq) {
        int w2 = wid - 2;
        int cs = w2 & 1, rg = w2 >> 1;
        int c = ts + cs * 32 + lane;
        bool cok = (c < Nq);
        float cv[8];
        if (cok) {
          #pragma unroll
          for (int t = 0; t < 8; ++t) cv[t] = sm->W[c * LDW + kp + t];
        }
        for (int r = ts + rg; r < 66; r += 7) {
          if (cok && (r >= Nq || c <= r)) {
            float acc = 0.f;
            #pragma unroll
            for (int t = 0; t < 8; ++t)
              acc += sm->W[r * LDW + kp + t] * cv[t];
            sm->W[r * LDW + c] -= acc;
          }
        }
      }
      __syncthreads();  // SB

      // T3: panel solve (rows below panel + 2 augmented rows), all p
      {
        const int m = Nq - ts;   // 0 at p==7
        int r = -1;
        if (tid < m) r = ts + tid;
        else if (tid < m + 2) r = 64 + (tid - m);
        if (r >= 0) {
          float v[8];
          #pragma unroll
          for (int c = 0; c < 8; ++c) v[c] = sm->W[r * LDW + k0 + c];
          #pragma unroll
          for (int j = 0; j < 8; ++j) {
            float acc = v[j];
            #pragma unroll
            for (int q = 0; q < j; ++q)
              acc -= v[q] * sm->W[(k0 + j) * LDW + k0 + q];
            v[j] = acc * sm->cid[k0 + j];
          }
          #pragma unroll
          for (int c = 0; c < 8; ++c) sm->W[r * LDW + k0 + c] = v[c];
        }
        __syncthreads();  // SC
      }
    }

    // ---- P5b: backward solves in parallel (warp0: x1, warp1: x2) ----
    if (wid <= 1) {
      const int rowi = 64 + wid;
      float xa = sm->W[rowi * LDW + lane];
      float xb = sm->W[rowi * LDW + lane + 32];
      for (int k = 63; k >= 33; k -= 2) {
        float ck0 = sm->cid[k], ck1 = sm->cid[k - 1];
        float Lk = sm->W[k * LDW + k - 1];
        float y0 = __shfl_sync(FULL, xb, k - 32) * ck0;
        float t1 = __shfl_sync(FULL, xb, k - 33);
        float y1 = (t1 - Lk * y0) * ck1;
        if (lane == k - 32) xb = y0;
        if (lane == k - 33) xb = y1;
        float wa0 = sm->W[k * LDW + lane];
        float wa1 = sm->W[(k - 1) * LDW + lane];
        float wb0 = (lane + 32 < k - 1) ? sm->W[k * LDW + lane + 32]       : 0.f;
        float wb1 = (lane + 32 < k - 1) ? sm->W[(k - 1) * LDW + lane + 32] : 0.f;
        xa -= wa0 * y0 + wa1 * y1;
        xb -= wb0 * y0 + wb1 * y1;
      }
      for (int k = 31; k >= 1; k -= 2) {
        float ck0 = sm->cid[k], ck1 = sm->cid[k - 1];
        float Lk = sm->W[k * LDW + k - 1];
        float y0 = __shfl_sync(FULL, xa, k) * ck0;
        float t1 = __shfl_sync(FULL, xa, k - 1);
        float y1 = (t1 - Lk * y0) * ck1;
        if (lane == k)     xa = y0;
        if (lane == k - 1) xa = y1;
        float wa0 = (lane < k - 1) ? sm->W[k * LDW + lane]       : 0.f;
        float wa1 = (lane < k - 1) ? sm->W[(k - 1) * LDW + lane] : 0.f;
        xa -= wa0 * y0 + wa1 * y1;
      }
      if (wid == 1) { sm->r1[lane] = xa; sm->r1[lane + 32] = xb; }
      asm volatile("bar.sync 1, 64;" ::: "memory");
      if (wid == 0) {
        float x2a = sm->r1[lane], x2b = sm->r1[lane + 32];
        float g1 = sm->gvec[lane] * xa + sm->gvec[lane + 32] * xb;
        float g2 = sm->gvec[lane] * x2a + sm->gvec[lane + 32] * x2b;
        #pragma unroll
        for (int o = 16; o; o >>= 1) {
          g1 += __shfl_down_sync(FULL, g1, o);
          g2 += __shfl_down_sync(FULL, g2, o);
        }
        g1 = __shfl_sync(FULL, g1, 0);
        g2 = __shfl_sync(FULL, g2, 0);
        float dyf = (r2v - g1) / (gam - g2);
        sm->dyv[64 + lane] = xa - dyf * x2a;
        sm->dyv[96 + lane] = xb - dyf * x2b;
        if (lane == 0) sm->dyv[128] = dyf;
      }
    }
    __syncthreads();  // B5

    // ---- P6: row duals ----
    {
      float dyf = sm->dyv[128];
      float dca = sm->dyv[64 + lane], dcb = sm->dyv[96 + lane];
      #pragma unroll
      for (int rr4 = 0; rr4 < 4; ++rr4) {
        int i = wid * 4 + rr4;
        float dot = sm->dv[i * 64 + lane] * dca + sm->dv[i * 64 + lane + 32] * dcb;
        #pragma unroll
        for (int o = 16; o; o >>= 1) dot += __shfl_down_sync(FULL, dot, o);
        if (lane == 0)
          sm->dyv[i] = (sm->rr[i] - dot - sm->av[i] * dyf) * sm->iu[i];
      }
    }
    __syncthreads();  // B6

    // ---- P7: dz + step length ----
    float amin = 1e30f;
    {
      float maxs = 1e-30f;
      float dyf = sm->dyv[128];
      float dyc = sm->dyv[64 + jc];
      #pragma unroll
      for (int j = 0; j < 8; ++j) {
        int i = ib + 8 * j, k = tid + NT * j;
        float atd = sm->dyv[i] + dyc + dyf * fe[j];
        float dzk = (sm->rz[k] - atd) * sm->dv[k];
        dzr[j] = dzk;
        float ds1 = zr[j] - s1[j] + dzk;
        float ds2 = 1.f - zr[j] - s2[j] - dzk;
        float dl1 = smu * is1[j] - l1[j] - l1[j] * ds1 * is1[j];
        float dl2 = smu * is2[j] - l2[j] - l2[j] * ds2 * is2[j];
        maxs = fmaxf(maxs, fmaxf(-ds1 * is1[j], -ds2 * is2[j]));
        if (dl1 < 0.f) amin = fminf(amin, __fdividef(l1[j], -dl1));
        if (dl2 < 0.f) amin = fminf(amin, __fdividef(l2[j], -dl2));
      }
      amin = fminf(amin, __fdividef(1.f, maxs));
    }
    #pragma unroll
    for (int o = 16; o; o >>= 1) amin = fminf(amin, __shfl_down_sync(FULL, amin, o));
    if (lane == 0) sm->red[48 + wid] = amin;
    __syncthreads();  // B7
    float am = 1e30f;
    #pragma unroll
    for (int w = 0; w < 16; ++w) am = fminf(am, sm->red[48 + w]);
    const float alpha = fminf(1.f, 0.99f * am);

    // ---- P8: update + mu accumulation ----
    float sl = 0.f;
    #pragma unroll
    for (int j = 0; j < 8; ++j) {
      int k = tid + NT * j;
      float dzk = dzr[j];
      float ds1 = zr[j] - s1[j] + dzk;
      float ds2 = 1.f - zr[j] - s2[j] - dzk;
      float dl1 = smu * is1[j] - l1[j] - l1[j] * ds1 * is1[j];
      float dl2 = smu * is2[j] - l2[j] - l2[j] * ds2 * is2[j];
      zr[j] += alpha * dzk;
      s1[j] += alpha * ds1;  s2[j] += alpha * ds2;
      l1[j] += alpha * dl1;  l2[j] += alpha * dl2;
      sm->z[k] = zr[j];
      sl += s1[j] * l1[j] + s2[j] * l2[j];
    }
    if (tid < 129) sm->y[tid] += alpha * sm->dyv[tid];
    #pragma unroll
    for (int o = 16; o; o >>= 1) sl += __shfl_down_sync(FULL, sl, o);
    if (lane == 0) sm->red[32 + wid] = sl;
    __syncthreads();  // B8
    musum = 0.f;
    #pragma unroll
    for (int w = 0; w < 16; ++w) musum += sm->red[32 + w];
  }

  #pragma unroll
  for (int j = 0; j < 8; ++j)
    out[b * NXq + tid + NT * j] = zr[j];
}

extern "C" void kernel_launch(void* const* d_in, const int* in_sizes, int n_in,
                              void* d_out, int out_size) {
  const float* x    = (const float*)d_in[0];
  const float* gid  = (const float*)d_in[1];
  const float* expo = (const float*)d_in[2];
  float* out = (float*)d_out;
  size_t smem = sizeof(SMem);
  cudaFuncSetAttribute(qp_ipm_kernel,
                       cudaFuncAttributeMaxDynamicSharedMemorySize, (int)smem);
  qp_ipm_kernel<<<NB, NT, smem>>>(x, gid, expo, out);
}